// round 5
// baseline (speedup 1.0000x reference)
#include <cuda_runtime.h>
#include <cuda_fp16.h>
#include <cstdint>

// ---------------- problem constants ----------------
static constexpr int BS    = 32;
static constexpr int RB    = 128;   // row blocks
static constexpr int CBLK  = 128;   // col blocks
static constexpr int PAIRS = 7;     // ceil(13/2) col-block pairs (padded)
static constexpr int SLOTS = 14;    // padded nnz slots per row
static constexpr int NCOL  = CBLK * BS;   // 4096
static constexpr int MAXBATCH = 2048;
static constexpr int MT    = 256;   // batch rows per CTA
static constexpr int TPB   = 256;   // 8 warps; each warp computes m32 x n32
static constexpr int STAGES = 3;    // ring depth (A only)

// ---------------- device scratch (static, no allocation) ----------------
__device__ __align__(16) __half g_x16[(size_t)MAXBATCH * NCOL];      // 16 MB fp16 x
// B in mma-fragment order: per (rblk,pair) 4KB tile:
//   [ks(4)][h(2)][lane(32)] x uint4  (lane's 4 fragment regs b0..b3)
__device__ __align__(16) __half g_wpk[(size_t)RB * PAIRS * 2048];    // 3.5 MB
__device__ int g_pcols[RB * SLOTS];

// ---------------- PTX helpers (baseline PTX only) ----------------
__device__ __forceinline__ uint32_t smem_u32(const void* p) {
    uint32_t a;
    asm("{ .reg .u64 t; cvta.to.shared.u64 t, %1; cvt.u32.u64 %0, t; }" : "=r"(a) : "l"(p));
    return a;
}
__device__ __forceinline__ void cp_async16(uint32_t dst, const void* src) {
    asm volatile("cp.async.cg.shared.global [%0], [%1], 16;" :: "r"(dst), "l"(src));
}
__device__ __forceinline__ void cp_commit() {
    asm volatile("cp.async.commit_group;" ::: "memory");
}
template <int N>
__device__ __forceinline__ void cp_wait() {
    asm volatile("cp.async.wait_group %0;" :: "n"(N) : "memory");
}

// ---------------- prep kernels ----------------
__global__ void k_convert_x(const float* __restrict__ x, int n8) {
    int i = blockIdx.x * blockDim.x + threadIdx.x;
    if (i >= n8) return;
    const float4* x4 = reinterpret_cast<const float4*>(x);
    float4 a = x4[2 * i], b = x4[2 * i + 1];
    union { __half2 h2[4]; uint4 v; } u;
    u.h2[0] = __floats2half2_rn(a.x, a.y);
    u.h2[1] = __floats2half2_rn(a.z, a.w);
    u.h2[2] = __floats2half2_rn(b.x, b.y);
    u.h2[3] = __floats2half2_rn(b.z, b.w);
    reinterpret_cast<uint4*>(g_x16)[i] = u.v;
}

__global__ void k_prep_cols(const int* __restrict__ crow, const int* __restrict__ cols) {
    int i = blockIdx.x * blockDim.x + threadIdx.x;
    if (i >= RB * SLOTS) return;
    int r = i / SLOTS, s = i % SLOTS;
    int beg = crow[r];
    int len = crow[r + 1] - beg;
    g_pcols[i] = (s < len) ? cols[beg + s] : 0;
}

// Pack masked fp16 weights directly in mma.sync B-fragment order.
// Thread q (0..255): lane = q&31, idx = q>>5: ks = idx>>1, h = idx&1.
//   n  = h*16 + lane/4,  kb = ks*16 + (lane%4)*2   (k within the 64-wide stage)
//   uint4 = { {B[kb][n],B[kb+1][n]}, {B[kb+8][n],B[kb+9][n]},
//             {B[kb][n+8],B[kb+1][n+8]}, {B[kb+8][n+8],B[kb+9][n+8]} }
// where B[k][n] = mask*w of slot (2p + k/32), row n, col k%32.
__global__ void k_prep_w(const float* __restrict__ mask, const float* __restrict__ w,
                         const int* __restrict__ crow) {
    int tile = blockIdx.x;             // rblk*PAIRS + p
    int rblk = tile / PAIRS, p = tile % PAIRS;
    int q = threadIdx.x;
    int lane = q & 31, idx = q >> 5;
    int ks = idx >> 1, h = idx & 1;
    int n0 = h * 16 + (lane >> 2);
    int kb = ks * 16 + (lane & 3) * 2;
    int beg = crow[rblk];
    int len = crow[rblk + 1] - beg;

    union { __half hv[8]; uint4 v; } u;
#pragma unroll
    for (int r = 0; r < 4; r++) {          // r = (n offset 0/8) * 2 + (k offset 0/8)
        int n = n0 + (r >> 1) * 8;
        int k = kb + (r & 1) * 8;
#pragma unroll
        for (int e = 0; e < 2; e++) {
            int kk = k + e;
            int slot = 2 * p + (kk >> 5);
            float f = 0.0f;
            if (slot < len) {
                long el = (long)(beg + slot) * 1024 + n * 32 + (kk & 31);
                f = mask[el] * w[el];
            }
            u.hv[r * 2 + e] = __float2half_rn(f);
        }
    }
    reinterpret_cast<uint4*>(g_wpk)[(size_t)tile * 256 + q] = u.v;
}

// ---------------- main kernel ----------------
static constexpr int A_BYTES    = MT * 128;             // 32 KB per stage
static constexpr int SMEM_TOTAL = STAGES * A_BYTES;     // 96 KB -> 2 CTAs/SM

// Issue cp.async for stage p (A only) into ring slot.
__device__ __forceinline__ void issue_stage(uint32_t sb, int slot, int p, int tid,
                                            const __half* xb, const int* pc) {
    int c0 = __ldg(pc + 2 * p);
    int c1 = __ldg(pc + 2 * p + 1);
    uint32_t abase = sb + slot * A_BYTES;
#pragma unroll
    for (int t = tid; t < MT * 8; t += TPB) {
        int q = t & 3;          // 16B chunk within 64B half
        int h = (t >> 2) & 1;   // which col block of the pair
        int r = t >> 3;         // batch row within tile
        const __half* src = xb + (size_t)r * NCOL + (h ? c1 : c0) * BS + q * 8;
        uint32_t off = (uint32_t)(r * 128 + h * 64 + q * 16);
        uint32_t sw = off ^ ((off >> 3) & 0x70);
        cp_async16(abase + sw, src);
    }
    cp_commit();
}

// Compute one stage (K=64). B fragments loaded by coalesced LDG.128 from L2.
__device__ __forceinline__ void compute_stage(uint32_t sb, int slot, int wid, int lane,
                                              const uint4* __restrict__ wtile,
                                              float acc[2][4][4]) {
    // B: 8 uint4 per lane: [ks][h]
    uint4 b[8];
#pragma unroll
    for (int i = 0; i < 8; i++)
        b[i] = __ldg(wtile + i * 32 + lane);

    uint32_t abase = sb + slot * A_BYTES;
    int arow = lane & 15;
    int akb  = lane >> 4;

#pragma unroll
    for (int ks = 0; ks < 4; ks++) {
#pragma unroll
        for (int mi = 0; mi < 2; mi++) {
            uint32_t ao = (uint32_t)((mi * 128 + wid * 16 + arow) * 128 + akb * 16 + ks * 32);
            uint32_t aaddr = abase + (ao ^ ((ao >> 3) & 0x70));
            uint32_t a0, a1, a2, a3;
            asm volatile("ldmatrix.sync.aligned.m8n8.x4.shared.b16 {%0,%1,%2,%3}, [%4];"
                         : "=r"(a0), "=r"(a1), "=r"(a2), "=r"(a3) : "r"(aaddr));
#pragma unroll
            for (int nt = 0; nt < 4; nt++) {
                const uint4& bb = b[ks * 2 + (nt >> 1)];
                uint32_t b0 = (nt & 1) ? bb.z : bb.x;
                uint32_t b1 = (nt & 1) ? bb.w : bb.y;
                asm volatile(
                    "mma.sync.aligned.m16n8k16.row.col.f32.f16.f16.f32 "
                    "{%0,%1,%2,%3}, {%4,%5,%6,%7}, {%8,%9}, {%0,%1,%2,%3};"
                    : "+f"(acc[mi][nt][0]), "+f"(acc[mi][nt][1]),
                      "+f"(acc[mi][nt][2]), "+f"(acc[mi][nt][3])
                    : "r"(a0), "r"(a1), "r"(a2), "r"(a3), "r"(b0), "r"(b1));
            }
        }
    }
}

template <int P>
__device__ __forceinline__ void pipeline_stage(uint32_t sb, int wid, int lane, int tid,
                                               const __half* xb, const int* pc,
                                               const uint4* wbase, float acc[2][4][4]) {
    constexpr int WAITN = (PAIRS - 1 - P < STAGES - 1) ? (PAIRS - 1 - P) : (STAGES - 1);
    cp_wait<WAITN>();
    __syncthreads();
    compute_stage(sb, P % STAGES, wid, lane, wbase + (size_t)P * 256, acc);
    if (P + STAGES < PAIRS) {
        __syncthreads();   // all warps done reading this slot
        issue_stage(sb, P % STAGES, P + STAGES, tid, xb, pc);
    }
}

__global__ void __launch_bounds__(TPB, 2)
k_main(const float* __restrict__ bias, float* __restrict__ out) {
    extern __shared__ char smem[];
    uint32_t sb = smem_u32(smem);
    int tid = threadIdx.x;
    int wid = tid >> 5, lane = tid & 31;
    int mt = blockIdx.x;       // batch tile of MT rows
    int rblk = blockIdx.y;     // row block

    const __half* xb = g_x16 + (size_t)mt * MT * NCOL;
    const int* pc = g_pcols + rblk * SLOTS;
    const uint4* wbase = reinterpret_cast<const uint4*>(g_wpk) + (size_t)rblk * PAIRS * 256;

    // Prime the 3-deep ring.
    issue_stage(sb, 0, 0, tid, xb, pc);
    issue_stage(sb, 1, 1, tid, xb, pc);
    issue_stage(sb, 2, 2, tid, xb, pc);

    float acc[2][4][4];
#pragma unroll
    for (int m = 0; m < 2; m++)
#pragma unroll
        for (int i = 0; i < 4; i++)
#pragma unroll
            for (int j = 0; j < 4; j++) acc[m][i][j] = 0.0f;

    pipeline_stage<0>(sb, wid, lane, tid, xb, pc, wbase, acc);
    pipeline_stage<1>(sb, wid, lane, tid, xb, pc, wbase, acc);
    pipeline_stage<2>(sb, wid, lane, tid, xb, pc, wbase, acc);
    pipeline_stage<3>(sb, wid, lane, tid, xb, pc, wbase, acc);
    pipeline_stage<4>(sb, wid, lane, tid, xb, pc, wbase, acc);
    pipeline_stage<5>(sb, wid, lane, tid, xb, pc, wbase, acc);
    pipeline_stage<6>(sb, wid, lane, tid, xb, pc, wbase, acc);

    // Epilogue: c fragments -> global, + bias.
    int grp = lane >> 2, qid = lane & 3;
    const float* bb = bias + rblk * BS;
#pragma unroll
    for (int mi = 0; mi < 2; mi++) {
        int row0 = mt * MT + mi * 128 + wid * 16 + grp;
        float* obase = out + (size_t)row0 * NCOL + rblk * BS;
#pragma unroll
        for (int nt = 0; nt < 4; nt++) {
            int col = nt * 8 + 2 * qid;
            float2 bv = *reinterpret_cast<const float2*>(bb + col);
            float2 v0 = make_float2(acc[mi][nt][0] + bv.x, acc[mi][nt][1] + bv.y);
            float2 v1 = make_float2(acc[mi][nt][2] + bv.x, acc[mi][nt][3] + bv.y);
            *reinterpret_cast<float2*>(obase + col) = v0;
            *reinterpret_cast<float2*>(obase + 8 * (size_t)NCOL + col) = v1;
        }
    }
}

// ---------------- launch ----------------
extern "C" void kernel_launch(void* const* d_in, const int* in_sizes, int n_in,
                              void* d_out, int out_size) {
    const float* x      = (const float*)d_in[0];
    const int*   crow   = (const int*)d_in[1];
    const int*   cols   = (const int*)d_in[2];
    const float* mask   = (const float*)d_in[3];
    const float* weight = (const float*)d_in[4];
    const float* bias   = (const float*)d_in[5];
    float* out = (float*)d_out;

    int batch = in_sizes[0] / NCOL;   // 2048
    int n8 = (batch * NCOL) / 8;

    cudaFuncSetAttribute(k_main, cudaFuncAttributeMaxDynamicSharedMemorySize, SMEM_TOTAL);

    k_convert_x<<<(n8 + 255) / 256, 256>>>(x, n8);
    k_prep_cols<<<(RB * SLOTS + 255) / 256, 256>>>(crow, cols);
    k_prep_w<<<RB * PAIRS, 256>>>(mask, weight, crow);

    dim3 grid(batch / MT, RB);
    k_main<<<grid, TPB, SMEM_TOTAL>>>(bias, out);
}

// round 6
// speedup vs baseline: 1.0740x; 1.0740x over previous
#include <cuda_runtime.h>
#include <cuda_fp16.h>
#include <cstdint>

// ---------------- problem constants ----------------
static constexpr int BS    = 32;
static constexpr int RB    = 128;   // row blocks
static constexpr int CBLK  = 128;   // col blocks
static constexpr int PAIRS = 7;     // ceil(13/2) col-block pairs (padded)
static constexpr int SLOTS = 14;    // padded nnz slots per row
static constexpr int NCOL  = CBLK * BS;   // 4096
static constexpr int MAXBATCH = 2048;
static constexpr int MT    = 128;   // batch rows per CTA
static constexpr int TPB   = 128;   // 4 warps; warp w owns rows [32w,32w+32)
static constexpr int STAGES = 3;    // per-warp A ring depth

// ---------------- device scratch (static, no allocation) ----------------
__device__ __align__(16) __half g_x16[(size_t)MAXBATCH * NCOL];      // 16 MB fp16 x
// B in mma-fragment order: per (rblk,pair) 4KB tile:
//   [ks(4)][h(2)][lane(32)] x uint4  (lane's 4 fragment regs b0..b3)
__device__ __align__(16) __half g_wpk[(size_t)RB * PAIRS * 2048];    // 3.5 MB
__device__ int g_pcols[RB * SLOTS];

// ---------------- PTX helpers (baseline PTX only) ----------------
__device__ __forceinline__ uint32_t smem_u32(const void* p) {
    uint32_t a;
    asm("{ .reg .u64 t; cvta.to.shared.u64 t, %1; cvt.u32.u64 %0, t; }" : "=r"(a) : "l"(p));
    return a;
}
__device__ __forceinline__ void cp_async16(uint32_t dst, const void* src) {
    asm volatile("cp.async.cg.shared.global [%0], [%1], 16;" :: "r"(dst), "l"(src));
}
__device__ __forceinline__ void cp_commit() {
    asm volatile("cp.async.commit_group;" ::: "memory");
}
template <int N>
__device__ __forceinline__ void cp_wait() {
    asm volatile("cp.async.wait_group %0;" :: "n"(N) : "memory");
}

// ---------------- prep kernels ----------------
__global__ void k_convert_x(const float* __restrict__ x, int n8) {
    int i = blockIdx.x * blockDim.x + threadIdx.x;
    if (i >= n8) return;
    const float4* x4 = reinterpret_cast<const float4*>(x);
    float4 a = x4[2 * i], b = x4[2 * i + 1];
    union { __half2 h2[4]; uint4 v; } u;
    u.h2[0] = __floats2half2_rn(a.x, a.y);
    u.h2[1] = __floats2half2_rn(a.z, a.w);
    u.h2[2] = __floats2half2_rn(b.x, b.y);
    u.h2[3] = __floats2half2_rn(b.z, b.w);
    reinterpret_cast<uint4*>(g_x16)[i] = u.v;
}

__global__ void k_prep_cols(const int* __restrict__ crow, const int* __restrict__ cols) {
    int i = blockIdx.x * blockDim.x + threadIdx.x;
    if (i >= RB * SLOTS) return;
    int r = i / SLOTS, s = i % SLOTS;
    int beg = crow[r];
    int len = crow[r + 1] - beg;
    g_pcols[i] = (s < len) ? cols[beg + s] : 0;
}

// Pack masked fp16 weights directly in mma.sync B-fragment order (verified R5).
__global__ void k_prep_w(const float* __restrict__ mask, const float* __restrict__ w,
                         const int* __restrict__ crow) {
    int tile = blockIdx.x;             // rblk*PAIRS + p
    int rblk = tile / PAIRS, p = tile % PAIRS;
    int q = threadIdx.x;
    int lane = q & 31, idx = q >> 5;
    int ks = idx >> 1, h = idx & 1;
    int n0 = h * 16 + (lane >> 2);
    int kb = ks * 16 + (lane & 3) * 2;
    int beg = crow[rblk];
    int len = crow[rblk + 1] - beg;

    union { __half hv[8]; uint4 v; } u;
#pragma unroll
    for (int r = 0; r < 4; r++) {          // r = (n offset 0/8) * 2 + (k offset 0/8)
        int n = n0 + (r >> 1) * 8;
        int k = kb + (r & 1) * 8;
#pragma unroll
        for (int e = 0; e < 2; e++) {
            int kk = k + e;
            int slot = 2 * p + (kk >> 5);
            float f = 0.0f;
            if (slot < len) {
                long el = (long)(beg + slot) * 1024 + n * 32 + (kk & 31);
                f = mask[el] * w[el];
            }
            u.hv[r * 2 + e] = __float2half_rn(f);
        }
    }
    reinterpret_cast<uint4*>(g_wpk)[(size_t)tile * 256 + q] = u.v;
}

// ---------------- main kernel ----------------
static constexpr int WSLICE     = 32 * 128;               // 4 KB: one warp's A stage
static constexpr int WARP_SMEM  = STAGES * WSLICE;        // 12 KB per warp
static constexpr int SMEM_TOTAL = (TPB / 32) * WARP_SMEM; // 48 KB -> 3 CTAs/SM

// Per-warp: stage A slice for pair p into ring slot (8 cp.async per lane).
__device__ __forceinline__ void issue_stageW(uint32_t wbase, int slot, int p, int lane,
                                             const __half* xw, const int* pc) {
    int c0 = __ldg(pc + 2 * p);
    int c1 = __ldg(pc + 2 * p + 1);
    uint32_t abase = wbase + slot * WSLICE;
#pragma unroll
    for (int i = 0; i < 8; i++) {
        int t = lane + 32 * i;
        int q = t & 3;          // 16B chunk within 64B half
        int h = (t >> 2) & 1;   // which col block of the pair
        int r = t >> 3;         // row within warp's 32 rows
        const __half* src = xw + (size_t)r * NCOL + (h ? c1 : c0) * BS + q * 8;
        uint32_t off = (uint32_t)(r * 128 + h * 64 + q * 16);
        uint32_t sw = off ^ ((off >> 3) & 0x70);
        cp_async16(abase + sw, src);
    }
    cp_commit();
}

__device__ __forceinline__ void ldg_btile(const uint4* __restrict__ wtile, int lane, uint4 b[8]) {
#pragma unroll
    for (int i = 0; i < 8; i++)
        b[i] = __ldg(wtile + i * 32 + lane);
}

// Compute one stage (K=64): warp's m32 x n32 with B fragments in registers.
__device__ __forceinline__ void compute_stageW(uint32_t abase, int lane,
                                               const uint4 b[8], float acc[2][4][4]) {
    int arow = lane & 15;
    int akb  = lane >> 4;
#pragma unroll
    for (int ks = 0; ks < 4; ks++) {
#pragma unroll
        for (int mi = 0; mi < 2; mi++) {
            uint32_t ao = (uint32_t)((mi * 16 + arow) * 128 + akb * 16 + ks * 32);
            uint32_t aaddr = abase + (ao ^ ((ao >> 3) & 0x70));
            uint32_t a0, a1, a2, a3;
            asm volatile("ldmatrix.sync.aligned.m8n8.x4.shared.b16 {%0,%1,%2,%3}, [%4];"
                         : "=r"(a0), "=r"(a1), "=r"(a2), "=r"(a3) : "r"(aaddr));
#pragma unroll
            for (int nt = 0; nt < 4; nt++) {
                const uint4& bb = b[ks * 2 + (nt >> 1)];
                uint32_t b0 = (nt & 1) ? bb.z : bb.x;
                uint32_t b1 = (nt & 1) ? bb.w : bb.y;
                asm volatile(
                    "mma.sync.aligned.m16n8k16.row.col.f32.f16.f16.f32 "
                    "{%0,%1,%2,%3}, {%4,%5,%6,%7}, {%8,%9}, {%0,%1,%2,%3};"
                    : "+f"(acc[mi][nt][0]), "+f"(acc[mi][nt][1]),
                      "+f"(acc[mi][nt][2]), "+f"(acc[mi][nt][3])
                    : "r"(a0), "r"(a1), "r"(a2), "r"(a3), "r"(b0), "r"(b1));
            }
        }
    }
}

__global__ void __launch_bounds__(TPB, 3)
k_main(const float* __restrict__ bias, float* __restrict__ out) {
    extern __shared__ char smem[];
    uint32_t sb = smem_u32(smem);
    int tid = threadIdx.x;
    int wid = tid >> 5, lane = tid & 31;
    int mt = blockIdx.x;       // batch tile of MT rows
    int rblk = blockIdx.y;     // row block

    // Warp-private state: no __syncthreads anywhere.
    const __half* xw = g_x16 + ((size_t)mt * MT + wid * 32) * NCOL;
    const int* pc = g_pcols + rblk * SLOTS;
    const uint4* wtiles = reinterpret_cast<const uint4*>(g_wpk) + (size_t)rblk * PAIRS * 256;
    uint32_t wbase = sb + wid * WARP_SMEM;

    // Prime the per-warp 3-deep A ring.
    issue_stageW(wbase, 0, 0, lane, xw, pc);
    issue_stageW(wbase, 1, 1, lane, xw, pc);
    issue_stageW(wbase, 2, 2, lane, xw, pc);

    float acc[2][4][4];
#pragma unroll
    for (int m = 0; m < 2; m++)
#pragma unroll
        for (int i = 0; i < 4; i++)
#pragma unroll
            for (int j = 0; j < 4; j++) acc[m][i][j] = 0.0f;

    // B double-buffer in registers; prefetch one stage ahead.
    uint4 bbuf[2][8];
    ldg_btile(wtiles, lane, bbuf[0]);

#pragma unroll
    for (int p = 0; p < PAIRS; p++) {
        if (p + 1 < PAIRS)
            ldg_btile(wtiles + (size_t)(p + 1) * 256, lane, bbuf[(p + 1) & 1]);
        // Wait for this warp's stage-p cp.async group.
        if (p < PAIRS - STAGES + 1)      cp_wait<STAGES - 1>();
        else if (p == PAIRS - 2)         cp_wait<1>();
        else                             cp_wait<0>();
        __syncwarp();
        compute_stageW(wbase + (p % STAGES) * WSLICE, lane, bbuf[p & 1], acc);
        if (p + STAGES < PAIRS)
            issue_stageW(wbase, p % STAGES, p + STAGES, lane, xw, pc);
    }

    // Epilogue: warp-private rows; + bias.
    int grp = lane >> 2, qid = lane & 3;
    const float* bb = bias + rblk * BS;
#pragma unroll
    for (int mi = 0; mi < 2; mi++) {
        int row0 = mt * MT + wid * 32 + mi * 16 + grp;
        float* obase = out + (size_t)row0 * NCOL + rblk * BS;
#pragma unroll
        for (int nt = 0; nt < 4; nt++) {
            int col = nt * 8 + 2 * qid;
            float2 bv = *reinterpret_cast<const float2*>(bb + col);
            float2 v0 = make_float2(acc[mi][nt][0] + bv.x, acc[mi][nt][1] + bv.y);
            float2 v1 = make_float2(acc[mi][nt][2] + bv.x, acc[mi][nt][3] + bv.y);
            *reinterpret_cast<float2*>(obase + col) = v0;
            *reinterpret_cast<float2*>(obase + 8 * (size_t)NCOL + col) = v1;
        }
    }
}

// ---------------- launch ----------------
extern "C" void kernel_launch(void* const* d_in, const int* in_sizes, int n_in,
                              void* d_out, int out_size) {
    const float* x      = (const float*)d_in[0];
    const int*   crow   = (const int*)d_in[1];
    const int*   cols   = (const int*)d_in[2];
    const float* mask   = (const float*)d_in[3];
    const float* weight = (const float*)d_in[4];
    const float* bias   = (const float*)d_in[5];
    float* out = (float*)d_out;

    int batch = in_sizes[0] / NCOL;   // 2048
    int n8 = (batch * NCOL) / 8;

    cudaFuncSetAttribute(k_main, cudaFuncAttributeMaxDynamicSharedMemorySize, SMEM_TOTAL);

    k_convert_x<<<(n8 + 255) / 256, 256>>>(x, n8);
    k_prep_cols<<<(RB * SLOTS + 255) / 256, 256>>>(crow, cols);
    k_prep_w<<<RB * PAIRS, 256>>>(mask, weight, crow);

    dim3 grid(batch / MT, RB);
    k_main<<<grid, TPB, SMEM_TOTAL>>>(bias, out);
}

// round 7
// speedup vs baseline: 1.1847x; 1.1031x over previous
#include <cuda_runtime.h>
#include <cuda_fp16.h>
#include <cstdint>

// ---------------- problem constants ----------------
static constexpr int BS    = 32;
static constexpr int RB    = 128;   // row blocks
static constexpr int CBLK  = 128;   // col blocks
static constexpr int PAIRS = 7;     // ceil(13/2) col-block pairs (padded)
static constexpr int SLOTS = 14;    // padded nnz slots per row
static constexpr int NCOL  = CBLK * BS;   // 4096
static constexpr int MAXBATCH = 2048;
static constexpr int MT    = 128;   // batch rows per CTA
static constexpr int TPB   = 128;   // 4 warps; warp w owns rows [32w,32w+32)

// ---------------- device scratch (static, no allocation) ----------------
// x in mma A-fragment order: per (mtile=row/16, cblk) a 1KB tile:
//   [khalf(2)][lane(32)] x uint4; lane's uint4 = {a0,a1,a2,a3} halves:
//   a0 = x[R+g][C+2t..+1], a1 = row+8, a2 = col+8, a3 = both (+8,+8)
__device__ __align__(16) uint4 g_xf[(size_t)(MAXBATCH / 16) * CBLK * 64];   // 16 MB
// B in mma-fragment order: per (rblk,pair) 4KB tile: [ks(4)][h(2)][lane(32)] x uint4
__device__ __align__(16) uint4 g_wpk[(size_t)RB * PAIRS * 256];             // 3.5 MB
__device__ int g_pcols[RB * SLOTS];

// ---------------- prep kernels ----------------
// Shuffle fp32 x -> fp16 fragment-ordered g_xf. One warp-quarter (32 thr) per
// (tile, khalf): 4 coalesced float2 reads, 1 uint4 write per thread.
__global__ void k_convert_x(const float* __restrict__ x) {
    int uid  = blockIdx.x * 8 + (threadIdx.x >> 5);
    int lane = threadIdx.x & 31;
    int h    = uid & 1;
    int tile = uid >> 1;                 // mtile*128 + cblk
    int mtile = tile >> 7, cblk = tile & 127;
    int R = mtile * 16, C = cblk * 32 + h * 16;
    int g = lane >> 2, t = lane & 3;

    const float* xr = x + (size_t)(R + g) * NCOL + C + 2 * t;
    float2 f0 = *reinterpret_cast<const float2*>(xr);
    float2 f1 = *reinterpret_cast<const float2*>(xr + 8 * (size_t)NCOL);
    float2 f2 = *reinterpret_cast<const float2*>(xr + 8);
    float2 f3 = *reinterpret_cast<const float2*>(xr + 8 * (size_t)NCOL + 8);
    union { __half2 h2[4]; uint4 v; } u;
    u.h2[0] = __floats2half2_rn(f0.x, f0.y);
    u.h2[1] = __floats2half2_rn(f1.x, f1.y);
    u.h2[2] = __floats2half2_rn(f2.x, f2.y);
    u.h2[3] = __floats2half2_rn(f3.x, f3.y);
    g_xf[(size_t)tile * 64 + h * 32 + lane] = u.v;
}

// Pad out-of-range slots with the LAST valid col: duplicate loads hit the same
// L2 lines; the matching B half is zero so correctness is unaffected.
__global__ void k_prep_cols(const int* __restrict__ crow, const int* __restrict__ cols) {
    int i = blockIdx.x * blockDim.x + threadIdx.x;
    if (i >= RB * SLOTS) return;
    int r = i / SLOTS, s = i % SLOTS;
    int beg = crow[r];
    int len = crow[r + 1] - beg;
    g_pcols[i] = (s < len) ? cols[beg + s] : cols[beg + len - 1];
}

// Pack masked fp16 weights directly in mma.sync B-fragment order (verified R5/R6).
__global__ void k_prep_w(const float* __restrict__ mask, const float* __restrict__ w,
                         const int* __restrict__ crow) {
    int tile = blockIdx.x;             // rblk*PAIRS + p
    int rblk = tile / PAIRS, p = tile % PAIRS;
    int q = threadIdx.x;
    int lane = q & 31, idx = q >> 5;
    int ks = idx >> 1, h = idx & 1;
    int n0 = h * 16 + (lane >> 2);
    int kb = ks * 16 + (lane & 3) * 2;
    int beg = crow[rblk];
    int len = crow[rblk + 1] - beg;

    union { __half hv[8]; uint4 v; } u;
#pragma unroll
    for (int r = 0; r < 4; r++) {          // r = (n offset 0/8)*2 + (k offset 0/8)
        int n = n0 + (r >> 1) * 8;
        int k = kb + (r & 1) * 8;
#pragma unroll
        for (int e = 0; e < 2; e++) {
            int kk = k + e;
            int slot = 2 * p + (kk >> 5);
            float f = 0.0f;
            if (slot < len) {
                long el = (long)(beg + slot) * 1024 + n * 32 + (kk & 31);
                f = mask[el] * w[el];
            }
            u.hv[r * 2 + e] = __float2half_rn(f);
        }
    }
    g_wpk[(size_t)tile * 256 + q] = u.v;
}

// ---------------- main kernel: pure-register, no smem, no barriers ----------------
__global__ void __launch_bounds__(TPB, 4)
k_main(const float* __restrict__ bias, float* __restrict__ out) {
    int tid = threadIdx.x;
    int wid = tid >> 5, lane = tid & 31;
    int mt = blockIdx.x;       // batch tile of MT rows
    int rblk = blockIdx.y;     // row block

    const int* pc = g_pcols + rblk * SLOTS;
    const uint4* wt = g_wpk + (size_t)rblk * PAIRS * 256;
    // Warp owns mtiles (mt*8 + wid*2) and +1  (rows mt*128 + wid*32 .. +32)
    const uint4* xf = g_xf + ((size_t)mt * 8 + wid * 2) * CBLK * 64;

    float acc[2][4][4];
#pragma unroll
    for (int m = 0; m < 2; m++)
#pragma unroll
        for (int i = 0; i < 4; i++)
#pragma unroll
            for (int j = 0; j < 4; j++) acc[m][i][j] = 0.0f;

#pragma unroll 1
    for (int p = 0; p < PAIRS; p++) {
        int c0 = __ldg(pc + 2 * p);
        int c1 = __ldg(pc + 2 * p + 1);

        // A fragments: [mi][ks], ks = (cblk-of-pair)*2 + khalf. 8x LDG.128, coalesced.
        uint4 a[2][4];
#pragma unroll
        for (int mi = 0; mi < 2; mi++) {
            const uint4* base = xf + (size_t)mi * CBLK * 64;
            a[mi][0] = __ldg(base + (size_t)c0 * 64 + lane);
            a[mi][1] = __ldg(base + (size_t)c0 * 64 + 32 + lane);
            a[mi][2] = __ldg(base + (size_t)c1 * 64 + lane);
            a[mi][3] = __ldg(base + (size_t)c1 * 64 + 32 + lane);
        }
        // B fragments: 8x LDG.128, coalesced.
        uint4 b[8];
        const uint4* btile = wt + (size_t)p * 256;
#pragma unroll
        for (int i = 0; i < 8; i++)
            b[i] = __ldg(btile + i * 32 + lane);

#pragma unroll
        for (int ks = 0; ks < 4; ks++) {
#pragma unroll
            for (int mi = 0; mi < 2; mi++) {
                const uint4& av = a[mi][ks];
#pragma unroll
                for (int nt = 0; nt < 4; nt++) {
                    const uint4& bb = b[ks * 2 + (nt >> 1)];
                    uint32_t b0 = (nt & 1) ? bb.z : bb.x;
                    uint32_t b1 = (nt & 1) ? bb.w : bb.y;
                    asm volatile(
                        "mma.sync.aligned.m16n8k16.row.col.f32.f16.f16.f32 "
                        "{%0,%1,%2,%3}, {%4,%5,%6,%7}, {%8,%9}, {%0,%1,%2,%3};"
                        : "+f"(acc[mi][nt][0]), "+f"(acc[mi][nt][1]),
                          "+f"(acc[mi][nt][2]), "+f"(acc[mi][nt][3])
                        : "r"(av.x), "r"(av.y), "r"(av.z), "r"(av.w),
                          "r"(b0), "r"(b1));
                }
            }
        }
    }

    // Epilogue: warp-private rows; + bias.
    int grp = lane >> 2, qid = lane & 3;
    const float* bb = bias + rblk * BS;
#pragma unroll
    for (int mi = 0; mi < 2; mi++) {
        int row0 = mt * MT + wid * 32 + mi * 16 + grp;
        float* obase = out + (size_t)row0 * NCOL + rblk * BS;
#pragma unroll
        for (int nt = 0; nt < 4; nt++) {
            int col = nt * 8 + 2 * qid;
            float2 bv = *reinterpret_cast<const float2*>(bb + col);
            float2 v0 = make_float2(acc[mi][nt][0] + bv.x, acc[mi][nt][1] + bv.y);
            float2 v1 = make_float2(acc[mi][nt][2] + bv.x, acc[mi][nt][3] + bv.y);
            *reinterpret_cast<float2*>(obase + col) = v0;
            *reinterpret_cast<float2*>(obase + 8 * (size_t)NCOL + col) = v1;
        }
    }
}

// ---------------- launch ----------------
extern "C" void kernel_launch(void* const* d_in, const int* in_sizes, int n_in,
                              void* d_out, int out_size) {
    const float* x      = (const float*)d_in[0];
    const int*   crow   = (const int*)d_in[1];
    const int*   cols   = (const int*)d_in[2];
    const float* mask   = (const float*)d_in[3];
    const float* weight = (const float*)d_in[4];
    const float* bias   = (const float*)d_in[5];
    float* out = (float*)d_out;

    int batch = in_sizes[0] / NCOL;   // 2048

    // Fragment-shuffle x: one 32-thread unit per (mtile, cblk, khalf).
    int units = (batch / 16) * CBLK * 2;
    k_convert_x<<<units / 8, 256>>>(x);
    k_prep_cols<<<(RB * SLOTS + 255) / 256, 256>>>(crow, cols);
    k_prep_w<<<RB * PAIRS, 256>>>(mask, weight, crow);

    dim3 grid(batch / MT, RB);
    k_main<<<grid, TPB>>>(bias, out);
}

// round 8
// speedup vs baseline: 1.2256x; 1.0345x over previous
#include <cuda_runtime.h>
#include <cuda_fp16.h>
#include <cstdint>

// ---------------- problem constants ----------------
static constexpr int BS    = 32;
static constexpr int RB    = 128;   // row blocks
static constexpr int CBLK  = 128;   // col blocks
static constexpr int PAIRS = 7;     // ceil(13/2) col-block pairs (padded)
static constexpr int SLOTS = 14;    // padded nnz slots per row
static constexpr int NCOL  = CBLK * BS;   // 4096
static constexpr int MAXBATCH = 2048;
static constexpr int MT    = 128;   // batch rows per CTA
static constexpr int TPB   = 128;   // 4 warps; warp w owns rows [32w,32w+32)

// ---------------- device scratch (static, no allocation) ----------------
// x in mma A-fragment order: per (mtile=row/16, cblk) a 1KB tile:
//   [khalf(2)][lane(32)] x uint4; lane's uint4 = {a0,a1,a2,a3}
__device__ __align__(16) uint4 g_xf[(size_t)(MAXBATCH / 16) * CBLK * 64];   // 16 MB
// B in mma-fragment order: per (rblk,pair) 4KB tile: [ks(4)][h(2)][lane(32)] x uint4
__device__ __align__(16) uint4 g_wpk[(size_t)RB * PAIRS * 256];             // 3.5 MB
__device__ int g_pcols[RB * SLOTS];

// ---------------- PTX helpers ----------------
__device__ __forceinline__ uint32_t smem_u32(const void* p) {
    uint32_t a;
    asm("{ .reg .u64 t; cvta.to.shared.u64 t, %1; cvt.u32.u64 %0, t; }" : "=r"(a) : "l"(p));
    return a;
}
__device__ __forceinline__ void cp_async16(uint32_t dst, const void* src) {
    asm volatile("cp.async.cg.shared.global [%0], [%1], 16;" :: "r"(dst), "l"(src));
}
__device__ __forceinline__ void cp_commit() {
    asm volatile("cp.async.commit_group;" ::: "memory");
}
template <int N>
__device__ __forceinline__ void cp_wait() {
    asm volatile("cp.async.wait_group %0;" :: "n"(N) : "memory");
}
__device__ __forceinline__ void lds128(uint4& v, uint32_t addr) {
    asm volatile("ld.shared.v4.u32 {%0,%1,%2,%3}, [%4];"
                 : "=r"(v.x), "=r"(v.y), "=r"(v.z), "=r"(v.w) : "r"(addr));
}

// ---------------- prep kernels ----------------
// Shuffle fp32 x -> fp16 fragment-ordered g_xf (verified R7).
__global__ void k_convert_x(const float* __restrict__ x) {
    int uid  = blockIdx.x * 8 + (threadIdx.x >> 5);
    int lane = threadIdx.x & 31;
    int h    = uid & 1;
    int tile = uid >> 1;                 // mtile*128 + cblk
    int mtile = tile >> 7, cblk = tile & 127;
    int R = mtile * 16, C = cblk * 32 + h * 16;
    int g = lane >> 2, t = lane & 3;

    const float* xr = x + (size_t)(R + g) * NCOL + C + 2 * t;
    float2 f0 = *reinterpret_cast<const float2*>(xr);
    float2 f1 = *reinterpret_cast<const float2*>(xr + 8 * (size_t)NCOL);
    float2 f2 = *reinterpret_cast<const float2*>(xr + 8);
    float2 f3 = *reinterpret_cast<const float2*>(xr + 8 * (size_t)NCOL + 8);
    union { __half2 h2[4]; uint4 v; } u;
    u.h2[0] = __floats2half2_rn(f0.x, f0.y);
    u.h2[1] = __floats2half2_rn(f1.x, f1.y);
    u.h2[2] = __floats2half2_rn(f2.x, f2.y);
    u.h2[3] = __floats2half2_rn(f3.x, f3.y);
    g_xf[(size_t)tile * 64 + h * 32 + lane] = u.v;
}

// Pad out-of-range slots with the LAST valid col (dup loads share L2 lines; B half is 0).
__global__ void k_prep_cols(const int* __restrict__ crow, const int* __restrict__ cols) {
    int i = blockIdx.x * blockDim.x + threadIdx.x;
    if (i >= RB * SLOTS) return;
    int r = i / SLOTS, s = i % SLOTS;
    int beg = crow[r];
    int len = crow[r + 1] - beg;
    g_pcols[i] = (s < len) ? cols[beg + s] : cols[beg + len - 1];
}

// Pack masked fp16 weights in mma.sync B-fragment order (verified R5-R7).
__global__ void k_prep_w(const float* __restrict__ mask, const float* __restrict__ w,
                         const int* __restrict__ crow) {
    int tile = blockIdx.x;             // rblk*PAIRS + p
    int rblk = tile / PAIRS, p = tile % PAIRS;
    int q = threadIdx.x;
    int lane = q & 31, idx = q >> 5;
    int ks = idx >> 1, h = idx & 1;
    int n0 = h * 16 + (lane >> 2);
    int kb = ks * 16 + (lane & 3) * 2;
    int beg = crow[rblk];
    int len = crow[rblk + 1] - beg;

    union { __half hv[8]; uint4 v; } u;
#pragma unroll
    for (int r = 0; r < 4; r++) {
        int n = n0 + (r >> 1) * 8;
        int k = kb + (r & 1) * 8;
#pragma unroll
        for (int e = 0; e < 2; e++) {
            int kk = k + e;
            int slot = 2 * p + (kk >> 5);
            float f = 0.0f;
            if (slot < len) {
                long el = (long)(beg + slot) * 1024 + n * 32 + (kk & 31);
                f = mask[el] * w[el];
            }
            u.hv[r * 2 + e] = __float2half_rn(f);
        }
    }
    g_wpk[(size_t)tile * 256 + q] = u.v;
}

// ---------------- main kernel ----------------
// A fragments for one stage: 8 coalesced LDG.128 into registers.
__device__ __forceinline__ void load_a(uint4 a[2][4], const uint4* __restrict__ xf,
                                       int c0, int c1, int lane) {
#pragma unroll
    for (int mi = 0; mi < 2; mi++) {
        const uint4* base = xf + (size_t)mi * CBLK * 64;
        a[mi][0] = __ldg(base + (size_t)c0 * 64 + lane);
        a[mi][1] = __ldg(base + (size_t)c0 * 64 + 32 + lane);
        a[mi][2] = __ldg(base + (size_t)c1 * 64 + lane);
        a[mi][3] = __ldg(base + (size_t)c1 * 64 + 32 + lane);
    }
}

__global__ void __launch_bounds__(TPB, 4)
k_main(const float* __restrict__ bias, float* __restrict__ out) {
    __shared__ __align__(16) uint4 sB[PAIRS * 256];   // 28 KB: all B tiles
    int tid = threadIdx.x;
    int wid = tid >> 5, lane = tid & 31;
    int mt = blockIdx.x;       // batch tile of MT rows
    int rblk = blockIdx.y;     // row block

    const int* pc = g_pcols + rblk * SLOTS;
    const uint4* xf = g_xf + ((size_t)mt * 8 + wid * 2) * CBLK * 64;

    // Stage all 7 B tiles into smem (L2-resident source; 14 cp.async per thread).
    {
        const uint4* wt = g_wpk + (size_t)rblk * PAIRS * 256;
        uint32_t sbB = smem_u32(sB);
#pragma unroll
        for (int t = tid; t < PAIRS * 256; t += TPB)
            cp_async16(sbB + t * 16, wt + t);
        cp_commit();
    }

    // A double-buffer in registers; prime stage 0 (overlaps with B staging).
    uint4 a[2][2][4];
    load_a(a[0], xf, __ldg(pc + 0), __ldg(pc + 1), lane);

    float acc[2][4][4];
#pragma unroll
    for (int m = 0; m < 2; m++)
#pragma unroll
        for (int i = 0; i < 4; i++)
#pragma unroll
            for (int j = 0; j < 4; j++) acc[m][i][j] = 0.0f;

    cp_wait<0>();
    __syncthreads();

    uint32_t sbB = smem_u32(sB);
#pragma unroll
    for (int p = 0; p < PAIRS; p++) {
        // Prefetch next stage's A while computing this one.
        if (p + 1 < PAIRS)
            load_a(a[(p + 1) & 1], xf, __ldg(pc + 2 * p + 2), __ldg(pc + 2 * p + 3), lane);

        uint32_t bbase = sbB + p * 4096 + lane * 16;
#pragma unroll
        for (int ks = 0; ks < 4; ks++) {
            uint4 b0, b1;
            lds128(b0, bbase + (ks * 2 + 0) * 512);
            lds128(b1, bbase + (ks * 2 + 1) * 512);
#pragma unroll
            for (int mi = 0; mi < 2; mi++) {
                const uint4& av = a[p & 1][mi][ks];
#pragma unroll
                for (int nt = 0; nt < 4; nt++) {
                    const uint4& bb = (nt >> 1) ? b1 : b0;
                    uint32_t r0 = (nt & 1) ? bb.z : bb.x;
                    uint32_t r1 = (nt & 1) ? bb.w : bb.y;
                    asm volatile(
                        "mma.sync.aligned.m16n8k16.row.col.f32.f16.f16.f32 "
                        "{%0,%1,%2,%3}, {%4,%5,%6,%7}, {%8,%9}, {%0,%1,%2,%3};"
                        : "+f"(acc[mi][nt][0]), "+f"(acc[mi][nt][1]),
                          "+f"(acc[mi][nt][2]), "+f"(acc[mi][nt][3])
                        : "r"(av.x), "r"(av.y), "r"(av.z), "r"(av.w),
                          "r"(r0), "r"(r1));
                }
            }
        }
    }

    // Epilogue: warp-private rows; + bias.
    int grp = lane >> 2, qid = lane & 3;
    const float* bb = bias + rblk * BS;
#pragma unroll
    for (int mi = 0; mi < 2; mi++) {
        int row0 = mt * MT + wid * 32 + mi * 16 + grp;
        float* obase = out + (size_t)row0 * NCOL + rblk * BS;
#pragma unroll
        for (int nt = 0; nt < 4; nt++) {
            int col = nt * 8 + 2 * qid;
            float2 bv = *reinterpret_cast<const float2*>(bb + col);
            float2 v0 = make_float2(acc[mi][nt][0] + bv.x, acc[mi][nt][1] + bv.y);
            float2 v1 = make_float2(acc[mi][nt][2] + bv.x, acc[mi][nt][3] + bv.y);
            *reinterpret_cast<float2*>(obase + col) = v0;
            *reinterpret_cast<float2*>(obase + 8 * (size_t)NCOL + col) = v1;
        }
    }
}

// ---------------- launch ----------------
extern "C" void kernel_launch(void* const* d_in, const int* in_sizes, int n_in,
                              void* d_out, int out_size) {
    const float* x      = (const float*)d_in[0];
    const int*   crow   = (const int*)d_in[1];
    const int*   cols   = (const int*)d_in[2];
    const float* mask   = (const float*)d_in[3];
    const float* weight = (const float*)d_in[4];
    const float* bias   = (const float*)d_in[5];
    float* out = (float*)d_out;

    int batch = in_sizes[0] / NCOL;   // 2048

    int units = (batch / 16) * CBLK * 2;
    k_convert_x<<<units / 8, 256>>>(x);
    k_prep_cols<<<(RB * SLOTS + 255) / 256, 256>>>(crow, cols);
    k_prep_w<<<RB * PAIRS, 256>>>(mask, weight, crow);

    dim3 grid(batch / MT, RB);
    k_main<<<grid, TPB>>>(bias, out);
}

// round 9
// speedup vs baseline: 1.2585x; 1.0268x over previous
#include <cuda_runtime.h>
#include <cuda_fp16.h>
#include <cstdint>

// ---------------- problem constants ----------------
static constexpr int BS    = 32;
static constexpr int RB    = 128;   // row blocks
static constexpr int CBLK  = 128;   // col blocks
static constexpr int PAIRS = 7;     // ceil(13/2) col-block pairs (padded)
static constexpr int SLOTS = 14;    // padded nnz slots per row
static constexpr int NCOL  = CBLK * BS;   // 4096
static constexpr int MAXBATCH = 2048;
static constexpr int MT    = 256;   // batch rows per CTA
static constexpr int TPB   = 128;   // 4 warps; warp w owns rows [64w, 64w+64)

// ---------------- device scratch (static, no allocation) ----------------
// x in mma A-fragment order: per (mtile=row/16, cblk) a 1KB tile:
//   [khalf(2)][lane(32)] x uint4; lane's uint4 = {a0,a1,a2,a3}
__device__ __align__(16) uint4 g_xf[(size_t)(MAXBATCH / 16) * CBLK * 64];   // 16 MB
// B in mma-fragment order: per (rblk,pair) 4KB tile: [ks(4)][h(2)][lane(32)] x uint4
__device__ __align__(16) uint4 g_wpk[(size_t)RB * PAIRS * 256];             // 3.5 MB
__device__ int g_pcols[RB * SLOTS];

// ---------------- PTX helpers ----------------
__device__ __forceinline__ uint32_t smem_u32(const void* p) {
    uint32_t a;
    asm("{ .reg .u64 t; cvta.to.shared.u64 t, %1; cvt.u32.u64 %0, t; }" : "=r"(a) : "l"(p));
    return a;
}
__device__ __forceinline__ void cp_async16(uint32_t dst, const void* src) {
    asm volatile("cp.async.cg.shared.global [%0], [%1], 16;" :: "r"(dst), "l"(src));
}
__device__ __forceinline__ void cp_commit() {
    asm volatile("cp.async.commit_group;" ::: "memory");
}
template <int N>
__device__ __forceinline__ void cp_wait() {
    asm volatile("cp.async.wait_group %0;" :: "n"(N) : "memory");
}
__device__ __forceinline__ void lds128(uint4& v, uint32_t addr) {
    asm volatile("ld.shared.v4.u32 {%0,%1,%2,%3}, [%4];"
                 : "=r"(v.x), "=r"(v.y), "=r"(v.z), "=r"(v.w) : "r"(addr));
}

// ---------------- fused prep kernel ----------------
// Blocks [0, nconv): fragment-shuffle x (8 warp-units per block).
// Blocks [nconv, nconv+RB*PAIRS): pack weights (1 tile per block).
// Block nconv+RB*PAIRS: pad col table.
__global__ void k_prep(const float* __restrict__ x,
                       const int* __restrict__ crow, const int* __restrict__ cols,
                       const float* __restrict__ mask, const float* __restrict__ w,
                       int nconv) {
    int blk = blockIdx.x;
    if (blk < nconv) {
        // ---- convert x -> g_xf (fragment order, verified R7/R8) ----
        int uid  = blk * 8 + (threadIdx.x >> 5);
        int lane = threadIdx.x & 31;
        int h    = uid & 1;
        int tile = uid >> 1;                 // mtile*128 + cblk
        int mtile = tile >> 7, cblk = tile & 127;
        int R = mtile * 16, C = cblk * 32 + h * 16;
        int g = lane >> 2, t = lane & 3;

        const float* xr = x + (size_t)(R + g) * NCOL + C + 2 * t;
        float2 f0 = *reinterpret_cast<const float2*>(xr);
        float2 f1 = *reinterpret_cast<const float2*>(xr + 8 * (size_t)NCOL);
        float2 f2 = *reinterpret_cast<const float2*>(xr + 8);
        float2 f3 = *reinterpret_cast<const float2*>(xr + 8 * (size_t)NCOL + 8);
        union { __half2 h2[4]; uint4 v; } u;
        u.h2[0] = __floats2half2_rn(f0.x, f0.y);
        u.h2[1] = __floats2half2_rn(f1.x, f1.y);
        u.h2[2] = __floats2half2_rn(f2.x, f2.y);
        u.h2[3] = __floats2half2_rn(f3.x, f3.y);
        g_xf[(size_t)tile * 64 + h * 32 + lane] = u.v;
    } else if (blk < nconv + RB * PAIRS) {
        // ---- pack masked fp16 weights in B-fragment order (verified R5-R8) ----
        int tile = blk - nconv;            // rblk*PAIRS + p
        int rblk = tile / PAIRS, p = tile % PAIRS;
        int q = threadIdx.x;
        int lane = q & 31, idx = q >> 5;
        int ks = idx >> 1, h = idx & 1;
        int n0 = h * 16 + (lane >> 2);
        int kb = ks * 16 + (lane & 3) * 2;
        int beg = crow[rblk];
        int len = crow[rblk + 1] - beg;

        union { __half hv[8]; uint4 v; } u;
#pragma unroll
        for (int r = 0; r < 4; r++) {
            int n = n0 + (r >> 1) * 8;
            int k = kb + (r & 1) * 8;
#pragma unroll
            for (int e = 0; e < 2; e++) {
                int kk = k + e;
                int slot = 2 * p + (kk >> 5);
                float f = 0.0f;
                if (slot < len) {
                    long el = (long)(beg + slot) * 1024 + n * 32 + (kk & 31);
                    f = mask[el] * w[el];
                }
                u.hv[r * 2 + e] = __float2half_rn(f);
            }
        }
        g_wpk[(size_t)tile * 256 + q] = u.v;
    } else {
        // ---- pad col table with last valid col (B half is zero there) ----
        for (int i = threadIdx.x; i < RB * SLOTS; i += blockDim.x) {
            int r = i / SLOTS, s = i % SLOTS;
            int beg = crow[r];
            int len = crow[r + 1] - beg;
            g_pcols[i] = (s < len) ? cols[beg + s] : cols[beg + len - 1];
        }
    }
}

// ---------------- main kernel ----------------
// A fragments for one m-tile: 4 coalesced LDG.128.
__device__ __forceinline__ void load_a1(uint4 a[4], const uint4* __restrict__ base,
                                        int c0, int c1, int lane) {
    a[0] = __ldg(base + (size_t)c0 * 64 + lane);
    a[1] = __ldg(base + (size_t)c0 * 64 + 32 + lane);
    a[2] = __ldg(base + (size_t)c1 * 64 + lane);
    a[3] = __ldg(base + (size_t)c1 * 64 + 32 + lane);
}

__global__ void __launch_bounds__(TPB, 3)
k_main(const float* __restrict__ bias, float* __restrict__ out) {
    __shared__ __align__(16) uint4 sB[PAIRS * 256];   // 28 KB: all B tiles
    int tid = threadIdx.x;
    int wid = tid >> 5, lane = tid & 31;
    int mt = blockIdx.x;       // batch tile of MT rows
    int rblk = blockIdx.y;     // row block

    const int* pc = g_pcols + rblk * SLOTS;
    // Warp owns mtiles mt*16 + wid*4 .. +3  (rows mt*256 + wid*64 .. +64)
    const uint4* xf = g_xf + ((size_t)mt * 16 + wid * 4) * CBLK * 64;

    // Stage all 7 B tiles into smem (L2-resident source).
    {
        const uint4* wt = g_wpk + (size_t)rblk * PAIRS * 256;
        uint32_t sbB = smem_u32(sB);
#pragma unroll
        for (int t = tid; t < PAIRS * 256; t += TPB)
            cp_async16(sbB + t * 16, wt + t);
        cp_commit();
    }

    int c0 = __ldg(pc + 0), c1 = __ldg(pc + 1);
    // A double-buffer (one m-tile ahead); prime mi=0 of stage 0.
    uint4 a[2][4];
    load_a1(a[0], xf, c0, c1, lane);

    float acc[4][4][4];
#pragma unroll
    for (int m = 0; m < 4; m++)
#pragma unroll
        for (int i = 0; i < 4; i++)
#pragma unroll
            for (int j = 0; j < 4; j++) acc[m][i][j] = 0.0f;

    cp_wait<0>();
    __syncthreads();

    uint32_t sbB = smem_u32(sB);
#pragma unroll 1
    for (int p = 0; p < PAIRS; p++) {
        int c0n = 0, c1n = 0;
        if (p + 1 < PAIRS) { c0n = __ldg(pc + 2 * p + 2); c1n = __ldg(pc + 2 * p + 3); }

        // B for this stage: 8 LDS.128, reused across all 4 m-tiles.
        uint4 b[8];
        uint32_t bbase = sbB + p * 4096 + lane * 16;
#pragma unroll
        for (int i = 0; i < 8; i++)
            lds128(b[i], bbase + i * 512);

#pragma unroll
        for (int mi = 0; mi < 4; mi++) {
            // Prefetch next m-tile's A (crosses into next stage at mi=3).
            if (mi < 3)
                load_a1(a[(mi + 1) & 1], xf + (size_t)(mi + 1) * CBLK * 64, c0, c1, lane);
            else if (p + 1 < PAIRS)
                load_a1(a[0], xf, c0n, c1n, lane);

            const uint4* av = a[mi & 1];
#pragma unroll
            for (int ks = 0; ks < 4; ks++) {
#pragma unroll
                for (int nt = 0; nt < 4; nt++) {
                    const uint4& bb = b[ks * 2 + (nt >> 1)];
                    uint32_t r0 = (nt & 1) ? bb.z : bb.x;
                    uint32_t r1 = (nt & 1) ? bb.w : bb.y;
                    asm volatile(
                        "mma.sync.aligned.m16n8k16.row.col.f32.f16.f16.f32 "
                        "{%0,%1,%2,%3}, {%4,%5,%6,%7}, {%8,%9}, {%0,%1,%2,%3};"
                        : "+f"(acc[mi][nt][0]), "+f"(acc[mi][nt][1]),
                          "+f"(acc[mi][nt][2]), "+f"(acc[mi][nt][3])
                        : "r"(av[ks].x), "r"(av[ks].y), "r"(av[ks].z), "r"(av[ks].w),
                          "r"(r0), "r"(r1));
                }
            }
        }
        c0 = c0n; c1 = c1n;
    }

    // Epilogue: warp-private rows; + bias.
    int grp = lane >> 2, qid = lane & 3;
    const float* bb = bias + rblk * BS;
#pragma unroll
    for (int mi = 0; mi < 4; mi++) {
        int row0 = mt * MT + wid * 64 + mi * 16 + grp;
        float* obase = out + (size_t)row0 * NCOL + rblk * BS;
#pragma unroll
        for (int nt = 0; nt < 4; nt++) {
            int col = nt * 8 + 2 * qid;
            float2 bv = *reinterpret_cast<const float2*>(bb + col);
            float2 v0 = make_float2(acc[mi][nt][0] + bv.x, acc[mi][nt][1] + bv.y);
            float2 v1 = make_float2(acc[mi][nt][2] + bv.x, acc[mi][nt][3] + bv.y);
            *reinterpret_cast<float2*>(obase + col) = v0;
            *reinterpret_cast<float2*>(obase + 8 * (size_t)NCOL + col) = v1;
        }
    }
}

// ---------------- launch ----------------
extern "C" void kernel_launch(void* const* d_in, const int* in_sizes, int n_in,
                              void* d_out, int out_size) {
    const float* x      = (const float*)d_in[0];
    const int*   crow   = (const int*)d_in[1];
    const int*   cols   = (const int*)d_in[2];
    const float* mask   = (const float*)d_in[3];
    const float* weight = (const float*)d_in[4];
    const float* bias   = (const float*)d_in[5];
    float* out = (float*)d_out;

    int batch = in_sizes[0] / NCOL;   // 2048
    int nconv = batch * 2;            // convert blocks (8 warp-units each)

    k_prep<<<nconv + RB * PAIRS + 1, 256>>>(x, crow, cols, mask, weight, nconv);

    dim3 grid(batch / MT, RB);
    k_main<<<grid, TPB>>>(bias, out);
}